// round 14
// baseline (speedup 1.0000x reference)
#include <cuda_runtime.h>
#include <cstdint>

#define BATCH    512
#define BITD     64
#define NCLS     100
#define NTRAIN   100000
#define MARGIN_F 128.0f

#define GRID         1024
#define PACK_BLOCKS  391         // phase0: 256 rows each (16-row chunks x16)
#define UST_BLOCKS   505         // phase0: blocks 391..895
#define BATCH_BLOCKS 128         // phase0: blocks 896..1023 (4 rows each)
#define FIX_BLOCKS   512         // phase1: blocks 391..902
#define SCAN_BLOCKS  391         // phase1: blocks 0..390

#define Y_U4_TOTAL   (NTRAIN * 25)   // Y as uint4 count (400B rows)

// -------- device accumulators / scratch (no allocations allowed) --------
__device__ double   g_SUsq;            // fix-role |U'|^2 deltas only
__device__ double   g_corr;            // hinge corrections
__device__ double   g_SUpad[BITD * 16];// fix-role col deltas (padded lines)
__device__ float    g_usq[BATCH];      // per-row |u_b|^2
__device__ __align__(16) unsigned g_ypk[4 * BATCH];   // batch packs [word][row]
__device__ uint4    g_ypkN[NTRAIN];    // packed training labels
__device__ __align__(16) float g_supart[BATCH_BLOCKS * BITD]; // u col partials
__device__ float    g_uqpart[BATCH_BLOCKS];   // per-block |u|^2 partials
__device__ float    g_s2part[BATCH_BLOCKS];   // per-block s2 partials
__device__ __align__(16) float g_ucol[UST_BLOCKS * BITD]; // ust col partials
__device__ float    g_usqp[UST_BLOCKS];       // ust sq partials
__device__ unsigned g_bar;             // monotonic grid barrier (never reset)
__device__ unsigned g_done;            // monotonic finalize counter

__device__ __forceinline__ float wred(float v) {
#pragma unroll
    for (int o = 16; o; o >>= 1) v += __shfl_xor_sync(0xffffffffu, v, o);
    return v;
}
__device__ __forceinline__ double wredd(double v) {
#pragma unroll
    for (int o = 16; o; o >>= 1) v += __shfl_xor_sync(0xffffffffu, v, o);
    return v;
}

// --------- rare path: exact pair term 0.5*(max(m-d,0) - d) --------------
// Serial FMA chain -> identical FP order at both call sites: cancellation
// of the scan-side term by the fix-side subtraction is bit-exact.
__device__ __noinline__ double pair_term(int b, const float* __restrict__ ur,
                                         const float* __restrict__ vr) {
    float dot = 0.f, vsq = 0.f;
#pragma unroll 16
    for (int k = 0; k < BITD; k++) {
        float a = ur[k], c = vr[k];
        dot = fmaf(a, c, dot);
        vsq = fmaf(c, c, vsq);
    }
    float d = g_usq[b] - 2.f * dot + vsq;
    d = fmaxf(d, 0.f);
    return 0.5 * ((double)fmaxf(MARGIN_F - d, 0.f) - (double)d);
}

// Permuted pack mapping (identical everywhere): class c -> word (c&3),
// bit (c>>2). Set intersection is permutation-invariant.
template<int Q>
__device__ __forceinline__ void pack25(const unsigned* __restrict__ sw,
                                       unsigned& p0, unsigned& p1,
                                       unsigned& p2, unsigned& p3) {
#pragma unroll
    for (int i = 0; i < 25; i++) {
        const int c = Q * 25 + i;                 // compile-time
        const unsigned m = 1u << (c >> 2);
        if (__uint_as_float(sw[i]) != 0.f) {
            switch (c & 3) {
            case 0: p0 |= m; break;
            case 1: p1 |= m; break;
            case 2: p2 |= m; break;
            case 3: p3 |= m; break;
            }
        }
    }
}

// ballot pack for batch rows (lane l<25 covers classes 4l..4l+3 -> same map)
__device__ __forceinline__ uint4 pack_ballots(const float* __restrict__ row,
                                              int lane) {
    float4 v = make_float4(0.f, 0.f, 0.f, 0.f);
    if (lane < 25) v = ((const float4*)row)[lane];
    uint4 r;
    r.x = __ballot_sync(0xffffffffu, v.x != 0.f);
    r.y = __ballot_sync(0xffffffffu, v.y != 0.f);
    r.z = __ballot_sync(0xffffffffu, v.z != 0.f);
    r.w = __ballot_sync(0xffffffffu, v.w != 0.f);
    return r;
}

// ---- cp.async helpers ----
template<int N>
__device__ __forceinline__ void cp_wait() {
    asm volatile("cp.async.wait_group %0;" :: "n"(N) : "memory");
}
__device__ __forceinline__ void cp_commit() {
    asm volatile("cp.async.commit_group;" ::: "memory");
}
__device__ __forceinline__ void cp_cg16(unsigned sdst, const void* gsrc) {
    asm volatile("cp.async.cg.shared.global [%0], [%1], 16;"
                 :: "r"(sdst), "l"(gsrc) : "memory");
}

// =================== THE kernel: everything in one launch =================
__global__ void __launch_bounds__(256, 8)
k_all(const float* __restrict__ u, const float* __restrict__ y,
      const int* __restrict__ ind, const float* __restrict__ U,
      const float* __restrict__ Y, float* __restrict__ out) {
    // 13.2KB carved buffer:
    //   phase0 pack : ring of 2 x 400 uint4 (12.8KB)
    //   phase1 scan : 8KB word table
    //   phase1 fix  : 8KB table + 2KB sind
    __shared__ __align__(16) unsigned sbuf[3328];   // 13312 B
    __shared__ float    scol[BITD + 8];
    __shared__ unsigned yn4[4];
    __shared__ int      s_last;
    __shared__ int      s_flag;

    const int t    = threadIdx.x;
    const int lane = t & 31, warp = t >> 5;
    const int bid  = blockIdx.x;

    // ========================= PHASE 0 ===================================
    if (bid < PACK_BLOCKS) {
        // ---- pack role: 256 rows via cp.async ring of 16-row chunks ----
        const uint4* Y4 = (const uint4*)Y;
        unsigned sb = (unsigned)__cvta_generic_to_shared(sbuf);
        int base4 = bid * 6400;                   // 256 rows * 25 uint4

        auto issue = [&](int c) {
            unsigned dst = sb + (unsigned)(c & 1) * 6400u;   // bytes
            int g0 = base4 + c * 400;
            int g = g0 + t;
            if (g >= Y_U4_TOTAL) g = Y_U4_TOTAL - 1;
            cp_cg16(dst + (unsigned)t * 16u, Y4 + g);
            if (t < 144) {
                int g2 = g0 + 256 + t;
                if (g2 >= Y_U4_TOTAL) g2 = Y_U4_TOTAL - 1;
                cp_cg16(dst + (unsigned)(256 + t) * 16u, Y4 + g2);
            }
            cp_commit();
        };

        issue(0);
#pragma unroll 1
        for (int c = 0; c < 16; c++) {
            if (c < 15) { issue(c + 1); cp_wait<1>(); }
            else        { cp_wait<0>(); }
            __syncthreads();

            if (t < 64) {                          // 16 rows x 4 quarters
                const unsigned* sw = sbuf + (c & 1) * 1600 + t * 25;
                unsigned p0 = 0, p1 = 0, p2 = 0, p3 = 0;
                switch (t & 3) {
                case 0: pack25<0>(sw, p0, p1, p2, p3); break;
                case 1: pack25<1>(sw, p0, p1, p2, p3); break;
                case 2: pack25<2>(sw, p0, p1, p2, p3); break;
                default: pack25<3>(sw, p0, p1, p2, p3); break;
                }
                p0 |= __shfl_xor_sync(0xffffffffu, p0, 1);
                p0 |= __shfl_xor_sync(0xffffffffu, p0, 2);
                p1 |= __shfl_xor_sync(0xffffffffu, p1, 1);
                p1 |= __shfl_xor_sync(0xffffffffu, p1, 2);
                p2 |= __shfl_xor_sync(0xffffffffu, p2, 1);
                p2 |= __shfl_xor_sync(0xffffffffu, p2, 2);
                p3 |= __shfl_xor_sync(0xffffffffu, p3, 1);
                p3 |= __shfl_xor_sync(0xffffffffu, p3, 2);
                if ((t & 3) == 0) {
                    int nr = bid * 256 + c * 16 + (t >> 2);
                    if (nr < NTRAIN)
                        g_ypkN[nr] = make_uint4(p0, p1, p2, p3);
                }
            }
            __syncthreads();
        }
    } else if (bid < PACK_BLOCKS + UST_BLOCKS) {
        // ---- U stats role: flat float4 stream, per-block partials ----
        const int nth = UST_BLOCKS * 256;          // 129280; *4 % 64 == 0
        int ub  = bid - PACK_BLOCKS;               // 0..504
        int gid = ub * 256 + t;
        const float4* U4 = (const float4*)U;
        const int total4 = NTRAIN * BITD / 4;      // 1.6M

        float c0 = 0.f, c1 = 0.f, c2 = 0.f, c3 = 0.f, sq = 0.f;
#pragma unroll 4
        for (int i = gid; i < total4; i += nth) {
            float4 v = U4[i];
            c0 += v.x; c1 += v.y; c2 += v.z; c3 += v.w;
            sq += v.x * v.x + v.y * v.y + v.z * v.z + v.w * v.w;
        }
        int cbase = (4 * gid) & (BITD - 1);
        c0 += __shfl_xor_sync(0xffffffffu, c0, 16);
        c1 += __shfl_xor_sync(0xffffffffu, c1, 16);
        c2 += __shfl_xor_sync(0xffffffffu, c2, 16);
        c3 += __shfl_xor_sync(0xffffffffu, c3, 16);
        sq = wred(sq);

        if (t < BITD + 8) scol[t] = 0.f;
        __syncthreads();
        if (lane < 16) {
            atomicAdd(&scol[cbase],     c0);
            atomicAdd(&scol[cbase + 1], c1);
            atomicAdd(&scol[cbase + 2], c2);
            atomicAdd(&scol[cbase + 3], c3);
        }
        if (lane == 0) scol[BITD + warp] = sq;
        __syncthreads();
        if (t < BITD) g_ucol[ub * BITD + t] = scol[t];
        if (t == 0) {
            float s = 0.f;
#pragma unroll
            for (int w = 0; w < 8; w++) s += scol[BITD + w];
            g_usqp[ub] = s;
        }
    } else {
        // ---- batch role: 4 rows per block + zero fix accumulators ----
        int bb  = bid - PACK_BLOCKS - UST_BLOCKS;  // 0..127
        int row = bb * 4 + warp;

        if (t < BITD) scol[t] = 0.f;
        if (bb == 0) {
            if (t < BITD) g_SUpad[t * 16] = 0.0;
            if (t == 0) { g_SUsq = 0.0; g_corr = 0.0; }
        }
        __syncthreads();

        float2 v = ((const float2*)(u + row * BITD))[lane];
        float usq = v.x * v.x + v.y * v.y;
        float s2  = ((v.x > 0.f) ? 0.f : ((v.x < 0.f) ? 2.f : 1.f))
                  + ((v.y > 0.f) ? 0.f : ((v.y < 0.f) ? 2.f : 1.f));
        atomicAdd(&scol[2 * lane],     v.x);
        atomicAdd(&scol[2 * lane + 1], v.y);
        float usqr = wred(usq);
        float s2r  = wred(s2);
        if (lane == 0) {
            g_usq[row] = usqr;
            scol[BITD + warp] = usqr;
            scol[BITD + 4 + warp] = s2r;
        }

        uint4 b = pack_ballots(y + (size_t)row * NCLS, lane);
        if (lane == 0) {
            g_ypk[row]             = b.x;
            g_ypk[BATCH + row]     = b.y;
            g_ypk[2 * BATCH + row] = b.z;
            g_ypk[3 * BATCH + row] = b.w;
        }
        __syncthreads();

        if (t < BITD) g_supart[bb * BITD + t] = scol[t];
        if (t == 0) {
            g_uqpart[bb] = scol[BITD] + scol[BITD + 1]
                         + scol[BITD + 2] + scol[BITD + 3];
            g_s2part[bb] = scol[BITD + 4] + scol[BITD + 5]
                         + scol[BITD + 6] + scol[BITD + 7];
        }
    }

    // ================== grid barrier (monotonic epoch) ===================
    __syncthreads();
    __threadfence();
    if (t == 0) {
        unsigned old = atomicAdd(&g_bar, 1u);
        unsigned target = (old / GRID + 1u) * GRID;
        unsigned v;
        do {
            asm volatile("ld.global.acquire.gpu.u32 %0, [%1];"
                         : "=r"(v) : "l"(&g_bar));
            if (v < target) __nanosleep(64);
        } while (v < target);
    }
    __syncthreads();
    __threadfence();

    // ========================= PHASE 1 ===================================
    if (bid < SCAN_BLOCKS) {
        // ---- scan role ----
#pragma unroll
        for (int i = 0; i < 2; i++)
            ((uint4*)sbuf)[t + i * 256] = ((const uint4*)g_ypk)[t + i * 256];

        int n = bid * 256 + t;
        uint4 pk = make_uint4(0u, 0u, 0u, 0u);
        if (n < NTRAIN) pk = g_ypkN[n];
        unsigned w0 = pk.x, w1 = pk.y, w2 = pk.z, w3 = pk.w;
        __syncthreads();

        if (n < NTRAIN) {
            const unsigned* sh = sbuf;
            const uint4* sh4 = (const uint4*)sbuf;
            double corr = 0.0;
#pragma unroll 2
            for (int b0i = 0; b0i < BATCH; b0i += 16) {
                const uint4* p = sh4 + (b0i >> 2);
                uint4 pa = p[0], pb = p[1], pc = p[2], pd = p[3];
                unsigned m0g = min(min(pa.x & w0, pa.y & w0),
                                   min(pa.z & w0, pa.w & w0));
                unsigned m1g = min(min(pb.x & w0, pb.y & w0),
                                   min(pb.z & w0, pb.w & w0));
                unsigned m2g = min(min(pc.x & w0, pc.y & w0),
                                   min(pc.z & w0, pc.w & w0));
                unsigned m3g = min(min(pd.x & w0, pd.y & w0),
                                   min(pd.z & w0, pd.w & w0));
                if (min(min(m0g, m1g), min(m2g, m3g)) == 0u) {
#pragma unroll 1
                    for (int j = 0; j < 16; j++) {
                        int b = b0i + j;
                        unsigned r = (sh[b] & w0) | (sh[BATCH + b] & w1) |
                                     (sh[2 * BATCH + b] & w2) |
                                     (sh[3 * BATCH + b] & w3);
                        if (r == 0u)
                            corr += pair_term(b, u + b * BITD,
                                              U + (size_t)n * BITD);
                    }
                }
            }
            if (corr != 0.0) atomicAdd(&g_corr, corr);
        }
    } else if (bid < SCAN_BLOCKS + FIX_BLOCKS) {
        // ---- fix role: one batch row per block ----
        int i = bid - SCAN_BLOCKS;                 // 0..511
        unsigned* sht  = sbuf;                     // 8KB table
        int*      sind = (int*)(sbuf + 2048);      // 2KB

        sind[t]       = ind[t];
        sind[t + 256] = ind[t + 256];
#pragma unroll
        for (int j = 0; j < 2; j++)
            ((uint4*)sht)[t + j * 256] = ((const uint4*)g_ypk)[t + j * 256];
        if (t == 0) s_last = 1;
        __syncthreads();

        int n = sind[i];
        for (int j = i + 1 + t; j < BATCH; j += 256)
            if (sind[j] == n) s_last = 0;
        __syncthreads();

        if (s_last) {
            if (t == 0) {
                uint4 b = g_ypkN[n];
                yn4[0] = b.x; yn4[1] = b.y; yn4[2] = b.z; yn4[3] = b.w;
            }
            __syncthreads();

            unsigned yn0 = yn4[0], yn1 = yn4[1], yn2 = yn4[2], yn3 = yn4[3];
            unsigned m0 = sht[i],             m1 = sht[BATCH + i];
            unsigned m2 = sht[2 * BATCH + i], m3 = sht[3 * BATCH + i];
            double corr = 0.0;
#pragma unroll
            for (int bb = 0; bb < 2; bb++) {
                int b = t + bb * 256;
                unsigned ro = (sht[b] & yn0) | (sht[BATCH + b] & yn1) |
                              (sht[2 * BATCH + b] & yn2) |
                              (sht[3 * BATCH + b] & yn3);
                if (ro == 0u)
                    corr -= pair_term(b, u + b * BITD, U + (size_t)n * BITD);
                unsigned rn = (sht[b] & m0) | (sht[BATCH + b] & m1) |
                              (sht[2 * BATCH + b] & m2) |
                              (sht[3 * BATCH + b] & m3);
                if (rn == 0u)
                    corr += pair_term(b, u + b * BITD, u + i * BITD);
            }
            if (corr != 0.0) atomicAdd(&g_corr, corr);

            float dsq = 0.f;
            if (t < BITD) {
                float a = u[i * BITD + t];
                float c = U[(size_t)n * BITD + t];
                atomicAdd(&g_SUpad[t * 16], (double)(a - c));
                dsq = a * a - c * c;
                dsq = wred(dsq);
                if (lane == 0) atomicAdd(&g_SUsq, (double)dsq);
            }
        }
    }
    // blocks >= 903 do nothing in phase 1

    // ================= finalize: last block (monotonic counter) ==========
    __threadfence();
    __syncthreads();
    if (t == 0) {
        unsigned old = atomicAdd(&g_done, 1u);
        s_flag = ((old % GRID) == GRID - 1) ? 1 : 0;
    }
    __syncthreads();
    if (!s_flag) return;
    __threadfence();

    double* scolD = (double*)sbuf;          // [64] SU col sums
    double* suD   = scolD + BITD;           // [64] batch col sums
    __shared__ double sparts[12];           // usq(4) s2(4) Usq(4... use 12)

    if (t < 2 * BITD) ((double*)sbuf)[t] = 0.0;
    __syncthreads();

    {   // SU columns from 505 ust partials
        int col = t & 63, q = t >> 6;       // q in 0..3
        double s = 0.0;
        for (int i = q; i < UST_BLOCKS; i += 4)
            s += (double)g_ucol[i * BITD + col];
        atomicAdd(&scolD[col], s);
    }
    {   // su columns from 128 batch partials
        int col = t & 63, q = t >> 6;
        double s = 0.0;
        for (int i = q; i < BATCH_BLOCKS; i += 4)
            s += (double)g_supart[i * BITD + col];
        atomicAdd(&suD[col], s);
    }
    // sum_usq / s2 from batch partials (threads 0..127 -> warps 0..3)
    if (t < BATCH_BLOCKS) {
        double q = wredd((double)g_uqpart[t]);
        double a = wredd((double)g_s2part[t]);
        if (lane == 0) { sparts[warp] = q; sparts[4 + warp] = a; }
    }
    // U sq from 505 ust partials: threads cover stride 256
    {
        double s = 0.0;
        for (int i = t; i < UST_BLOCKS; i += 256) s += (double)g_usqp[i];
        s = wredd(s);
        if (lane == 0) sparts[8 + (warp & 3)] = 0.0;  // placeholder init
        __syncthreads();
        if (lane == 0) atomicAdd(&sparts[8 + (warp & 3)], s);
    }
    __syncthreads();

    if (t == 0) {
        double dotsum = 0.0;
#pragma unroll
        for (int k = 0; k < BITD; k++)
            dotsum += suD[k] * (scolD[k] + g_SUpad[k * 16]);
        double sum_usq = sparts[0] + sparts[1] + sparts[2] + sparts[3];
        double s2sum   = sparts[4] + sparts[5] + sparts[6] + sparts[7];
        double Usq     = sparts[8] + sparts[9] + sparts[10] + sparts[11]
                       + g_SUsq;
        double sum_dist = (double)NTRAIN * sum_usq
                        + (double)BATCH  * Usq
                        - 2.0 * dotsum;
        double loss1 = (0.5 * sum_dist + g_corr)
                     / ((double)BATCH * (double)NTRAIN);
        double loss2 = 0.1 * s2sum / ((double)BATCH * (double)BITD);
        out[0] = (float)(loss1 + loss2);
    }
}

// ------------------------------------------------------------ launcher
extern "C" void kernel_launch(void* const* d_in, const int* in_sizes, int n_in,
                              void* d_out, int out_size) {
    const float* u   = (const float*)d_in[0];   // [512, 64]
    const float* y   = (const float*)d_in[1];   // [512, 100]
    const int*   ind = (const int*)  d_in[2];   // [512]
    const float* U   = (const float*)d_in[3];   // [100000, 64]
    const float* Y   = (const float*)d_in[4];   // [100000, 100]
    float* out = (float*)d_out;

    k_all<<<GRID, 256>>>(u, y, ind, U, Y, out);
}

// round 15
// speedup vs baseline: 1.8713x; 1.8713x over previous
#include <cuda_runtime.h>
#include <cstdint>

#define BATCH    512
#define BITD     64
#define NCLS     100
#define NTRAIN   100000
#define MARGIN_F 128.0f

#define PACK_BLOCKS  391         // 256 rows per block
#define BATCH_BLOCKS 128         // 4 batch rows per block
#define PB_BLOCKS    (PACK_BLOCKS + BATCH_BLOCKS)

#define SCAN_BLOCKS  782         // 128 n per block, 2 threads per n
#define UST_BLOCKS   512
#define FIX_BLOCKS   512         // 1 batch row per block
#define MEGA_BLOCKS  (SCAN_BLOCKS + UST_BLOCKS + FIX_BLOCKS)

#define Y_U4_TOTAL   (NTRAIN * 25)   // Y as uint4 count (400B rows)

// -------- device accumulators / scratch (no allocations allowed) --------
__device__ double   g_SUsq;           // sum_n |U'_n|^2 (ust + fix deltas)
__device__ double   g_corr;           // hinge corrections over mismatch pairs
__device__ double   g_SUpad[BITD * 16]; // padded col sums (1 dbl / 128B line)
__device__ float    g_usq[BATCH];     // per-row |u_b|^2
__device__ __align__(16) unsigned g_ypk[4 * BATCH];  // batch packs [word][row]
__device__ uint4    g_ypkN[NTRAIN];   // packed training labels, one uint4/row
__device__ __align__(16) float g_supart[BATCH_BLOCKS * BITD]; // u col partials
__device__ float    g_uqpart[BATCH_BLOCKS];  // per-block sum |u|^2 partials
__device__ float    g_s2part[BATCH_BLOCKS];  // per-block s2 partials
__device__ unsigned g_done;           // k_mega completion counter

__device__ __forceinline__ float wred(float v) {
#pragma unroll
    for (int o = 16; o; o >>= 1) v += __shfl_xor_sync(0xffffffffu, v, o);
    return v;
}
__device__ __forceinline__ double wredd(double v) {
#pragma unroll
    for (int o = 16; o; o >>= 1) v += __shfl_xor_sync(0xffffffffu, v, o);
    return v;
}

// --------- rare path: exact pair term 0.5*(max(m-d,0) - d) --------------
// Serial FMA chain: identical FP-op order wherever compiled -> the
// add-then-subtract cancellation across scan/fix roles is bit-exact.
__device__ __noinline__ double pair_term(int b, const float* __restrict__ ur,
                                         const float* __restrict__ vr) {
    float dot = 0.f, vsq = 0.f;
#pragma unroll 16
    for (int k = 0; k < BITD; k++) {
        float a = ur[k], c = vr[k];
        dot = fmaf(a, c, dot);
        vsq = fmaf(c, c, vsq);
    }
    float d = g_usq[b] - 2.f * dot + vsq;
    d = fmaxf(d, 0.f);
    return 0.5 * ((double)fmaxf(MARGIN_F - d, 0.f) - (double)d);
}

// Permuted pack mapping (identical everywhere): class c -> word (c&3),
// bit (c>>2). Set intersection is permutation-invariant.
template<int Q>
__device__ __forceinline__ void pack25(const unsigned* __restrict__ sw,
                                       unsigned& p0, unsigned& p1,
                                       unsigned& p2, unsigned& p3) {
#pragma unroll
    for (int i = 0; i < 25; i++) {
        const int c = Q * 25 + i;                 // compile-time
        const unsigned m = 1u << (c >> 2);
        if (__uint_as_float(sw[i]) != 0.f) {
            switch (c & 3) {
            case 0: p0 |= m; break;
            case 1: p1 |= m; break;
            case 2: p2 |= m; break;
            case 3: p3 |= m; break;
            }
        }
    }
}

// ballot pack for the batch role (lane l<25 covers classes 4l..4l+3:
// word w bit l <- class 4l+w, same (c&3)/(c>>2) mapping)
__device__ __forceinline__ uint4 pack_ballots(const float* __restrict__ row,
                                              int lane) {
    float4 v = make_float4(0.f, 0.f, 0.f, 0.f);
    if (lane < 25) v = ((const float4*)row)[lane];
    uint4 r;
    r.x = __ballot_sync(0xffffffffu, v.x != 0.f);
    r.y = __ballot_sync(0xffffffffu, v.y != 0.f);
    r.z = __ballot_sync(0xffffffffu, v.z != 0.f);
    r.w = __ballot_sync(0xffffffffu, v.w != 0.f);
    return r;
}

// ---- cp.async helpers ----
template<int N>
__device__ __forceinline__ void cp_wait() {
    asm volatile("cp.async.wait_group %0;" :: "n"(N) : "memory");
}
__device__ __forceinline__ void cp_commit() {
    asm volatile("cp.async.commit_group;" ::: "memory");
}
__device__ __forceinline__ void cp_cg16(unsigned sdst, const void* gsrc) {
    asm volatile("cp.async.cg.shared.global [%0], [%1], 16;"
                 :: "r"(sdst), "l"(gsrc) : "memory");
}

// ------------- pack + batch kernel (R12, validated) ----------------------
__global__ void __launch_bounds__(256)
k_pb(const float* __restrict__ u, const float* __restrict__ y,
     const float* __restrict__ Y) {
    __shared__ __align__(16) unsigned sbuf[3 * 800 * 4];
    __shared__ float scol[BITD];
    __shared__ float sv[8];

    int t    = threadIdx.x;
    int lane = t & 31, warp = t >> 5;

    if (blockIdx.x < PACK_BLOCKS) {
        // ====================== pack role ================================
        const uint4* Y4 = (const uint4*)Y;
        unsigned sb = (unsigned)__cvta_generic_to_shared(sbuf);
        int base4 = blockIdx.x * 6400;            // 256 rows * 25 uint4

        auto issue = [&](int c) {
            unsigned dst = sb + (unsigned)(c % 3) * 12800u;
            int g0 = base4 + c * 800;
#pragma unroll
            for (int j = 0; j < 3; j++) {
                int k = t + j * 256;
                int g = g0 + k;
                if (g >= Y_U4_TOTAL) g = Y_U4_TOTAL - 1;
                cp_cg16(dst + (unsigned)k * 16u, Y4 + g);
            }
            if (t < 32) {
                int k = 768 + t;
                int g = g0 + k;
                if (g >= Y_U4_TOTAL) g = Y_U4_TOTAL - 1;
                cp_cg16(dst + (unsigned)k * 16u, Y4 + g);
            }
            cp_commit();
        };

        issue(0);
        issue(1);

#pragma unroll 1
        for (int c = 0; c < 8; c++) {
            if (c + 2 < 8) issue(c + 2);
            switch (7 - c) {
            case 0:  cp_wait<0>(); break;
            case 1:  cp_wait<1>(); break;
            default: cp_wait<2>(); break;
            }
            __syncthreads();

            if (t < 128) {
                const unsigned* bufw = sbuf + (c % 3) * 3200;
                const unsigned* sw = bufw + t * 25;
                unsigned p0 = 0, p1 = 0, p2 = 0, p3 = 0;
                switch (t & 3) {
                case 0: pack25<0>(sw, p0, p1, p2, p3); break;
                case 1: pack25<1>(sw, p0, p1, p2, p3); break;
                case 2: pack25<2>(sw, p0, p1, p2, p3); break;
                default: pack25<3>(sw, p0, p1, p2, p3); break;
                }
                p0 |= __shfl_xor_sync(0xffffffffu, p0, 1);
                p0 |= __shfl_xor_sync(0xffffffffu, p0, 2);
                p1 |= __shfl_xor_sync(0xffffffffu, p1, 1);
                p1 |= __shfl_xor_sync(0xffffffffu, p1, 2);
                p2 |= __shfl_xor_sync(0xffffffffu, p2, 1);
                p2 |= __shfl_xor_sync(0xffffffffu, p2, 2);
                p3 |= __shfl_xor_sync(0xffffffffu, p3, 1);
                p3 |= __shfl_xor_sync(0xffffffffu, p3, 2);
                if ((t & 3) == 0) {
                    int nr = blockIdx.x * 256 + c * 32 + (t >> 2);
                    if (nr < NTRAIN)
                        g_ypkN[nr] = make_uint4(p0, p1, p2, p3);
                }
            }
            __syncthreads();
        }
    } else {
        // ====================== batch role ===============================
        int bb  = blockIdx.x - PACK_BLOCKS;       // 0..127
        int row = bb * 4 + warp;                  // 0..511

        if (t < BITD) scol[t] = 0.f;
        if (bb == 0) {
            if (t < BITD) g_SUpad[t * 16] = 0.0;
            if (t == 0) { g_SUsq = 0.0; g_corr = 0.0; g_done = 0u; }
        }
        __syncthreads();

        float2 v = ((const float2*)(u + row * BITD))[lane];
        float usq = v.x * v.x + v.y * v.y;
        float s2  = ((v.x > 0.f) ? 0.f : ((v.x < 0.f) ? 2.f : 1.f))
                  + ((v.y > 0.f) ? 0.f : ((v.y < 0.f) ? 2.f : 1.f));
        atomicAdd(&scol[2 * lane],     v.x);
        atomicAdd(&scol[2 * lane + 1], v.y);
        float usqr = wred(usq);
        float s2r  = wred(s2);
        if (lane == 0) { g_usq[row] = usqr; sv[warp] = usqr; sv[4 + warp] = s2r; }

        uint4 b = pack_ballots(y + (size_t)row * NCLS, lane);
        if (lane == 0) {
            g_ypk[row]             = b.x;
            g_ypk[BATCH + row]     = b.y;
            g_ypk[2 * BATCH + row] = b.z;
            g_ypk[3 * BATCH + row] = b.w;
        }
        __syncthreads();

        if (t < BITD) g_supart[bb * BITD + t] = scol[t];
        if (t == 0) {
            g_uqpart[bb] = sv[0] + sv[1] + sv[2] + sv[3];
            g_s2part[bb] = sv[4] + sv[5] + sv[6] + sv[7];
        }
    }
}

// ------------- mega kernel: split-scan + U-stats + fix + finalize --------
__global__ void __launch_bounds__(256)
k_mega(const float* __restrict__ u, const int* __restrict__ ind,
       const float* __restrict__ U, const float* __restrict__ Y,
       float* __restrict__ out) {
    __shared__ __align__(16) unsigned sh[4 * BATCH];  // 8KB
    __shared__ int      sind[BATCH];
    __shared__ float    scol[BITD + 8];
    __shared__ unsigned yn4[4];
    __shared__ int      s_last;
    __shared__ int      s_flag;

    int t    = threadIdx.x;
    int lane = t & 31, warp = t >> 5;

    if (blockIdx.x < SCAN_BLOCKS) {
        // ====== scan role: 128 n per block, 2 threads per n ==============
#pragma unroll
        for (int i = 0; i < 2; i++)
            ((uint4*)sh)[t + i * 256] = ((const uint4*)g_ypk)[t + i * 256];

        int n    = blockIdx.x * 128 + (t & 127);  // both halves same n set
        int half = t >> 7;                        // 0: b 0..255, 1: b 256..511
        uint4 pk = make_uint4(0u, 0u, 0u, 0u);
        if (n < NTRAIN) pk = g_ypkN[n];           // coalesced (dup in L1)
        unsigned w0 = pk.x, w1 = pk.y, w2 = pk.z, w3 = pk.w;
        __syncthreads();

        if (n < NTRAIN) {
            const uint4* sh4 = (const uint4*)sh;  // word-0 table as uint4
            int bbase = half * 256;
            double corr = 0.0;
#pragma unroll 4
            for (int bo = 0; bo < 256; bo += 8) {
                int b0i = bbase + bo;
                uint4 pa = sh4[b0i >> 2];
                uint4 pb = sh4[(b0i >> 2) + 1];
                unsigned mna = min(min(pa.x & w0, pa.y & w0),
                                   min(pa.z & w0, pa.w & w0));
                unsigned mnb = min(min(pb.x & w0, pb.y & w0),
                                   min(pb.z & w0, pb.w & w0));
                if (min(mna, mnb) == 0u) {
#pragma unroll 1
                    for (int j = 0; j < 8; j++) {
                        int b = b0i + j;
                        unsigned r = (sh[b] & w0) | (sh[BATCH + b] & w1) |
                                     (sh[2 * BATCH + b] & w2) |
                                     (sh[3 * BATCH + b] & w3);
                        if (r == 0u)
                            corr += pair_term(b, u + b * BITD,
                                              U + (size_t)n * BITD);
                    }
                }
            }
            if (corr != 0.0) atomicAdd(&g_corr, corr);
        }
    } else if (blockIdx.x < SCAN_BLOCKS + UST_BLOCKS) {
        // ================= U stats role ==================================
        const int nth = UST_BLOCKS * 256;                 // 131072
        int gid = (blockIdx.x - SCAN_BLOCKS) * 256 + t;
        const float4* U4 = (const float4*)U;
        const int total4 = NTRAIN * BITD / 4;             // 1.6M

        float c0 = 0.f, c1 = 0.f, c2 = 0.f, c3 = 0.f, sq = 0.f;
#pragma unroll 4
        for (int i = gid; i < total4; i += nth) {
            float4 v = U4[i];
            c0 += v.x; c1 += v.y; c2 += v.z; c3 += v.w;
            sq += v.x * v.x + v.y * v.y + v.z * v.z + v.w * v.w;
        }
        int cbase = (4 * gid) & (BITD - 1);
        c0 += __shfl_xor_sync(0xffffffffu, c0, 16);
        c1 += __shfl_xor_sync(0xffffffffu, c1, 16);
        c2 += __shfl_xor_sync(0xffffffffu, c2, 16);
        c3 += __shfl_xor_sync(0xffffffffu, c3, 16);
        sq = wred(sq);

        if (t < BITD + 8) scol[t] = 0.f;
        __syncthreads();
        if (lane < 16) {
            atomicAdd(&scol[cbase],     c0);
            atomicAdd(&scol[cbase + 1], c1);
            atomicAdd(&scol[cbase + 2], c2);
            atomicAdd(&scol[cbase + 3], c3);
        }
        if (lane == 0) scol[BITD + warp] = sq;
        __syncthreads();
        if (t < BITD) atomicAdd(&g_SUpad[t * 16], (double)scol[t]);
        if (t == 0) {
            float s = 0.f;
#pragma unroll
            for (int w = 0; w < 8; w++) s += scol[BITD + w];
            atomicAdd(&g_SUsq, (double)s);
        }
    } else {
        // ================= fix role: one block per batch row =============
        int i = blockIdx.x - SCAN_BLOCKS - UST_BLOCKS;    // 0..511

        sind[t]       = ind[t];
        sind[t + 256] = ind[t + 256];
#pragma unroll
        for (int j = 0; j < 2; j++)
            ((uint4*)sh)[t + j * 256] = ((const uint4*)g_ypk)[t + j * 256];
        if (t == 0) s_last = 1;
        __syncthreads();

        int n = sind[i];
        for (int j = i + 1 + t; j < BATCH; j += 256)
            if (sind[j] == n) s_last = 0;
        __syncthreads();

        if (s_last) {
            if (t == 0) {
                uint4 b = g_ypkN[n];              // packed original Y row n
                yn4[0] = b.x; yn4[1] = b.y; yn4[2] = b.z; yn4[3] = b.w;
            }
            __syncthreads();

            unsigned yn0 = yn4[0], yn1 = yn4[1], yn2 = yn4[2], yn3 = yn4[3];
            unsigned m0 = sh[i],             m1 = sh[BATCH + i];
            unsigned m2 = sh[2 * BATCH + i], m3 = sh[3 * BATCH + i];
            double corr = 0.0;
#pragma unroll
            for (int bb = 0; bb < 2; bb++) {
                int b = t + bb * 256;
                unsigned ro = (sh[b] & yn0) | (sh[BATCH + b] & yn1) |
                              (sh[2 * BATCH + b] & yn2) |
                              (sh[3 * BATCH + b] & yn3);
                if (ro == 0u)   // remove scan's old-data contribution
                    corr -= pair_term(b, u + b * BITD, U + (size_t)n * BITD);
                unsigned rn = (sh[b] & m0) | (sh[BATCH + b] & m1) |
                              (sh[2 * BATCH + b] & m2) |
                              (sh[3 * BATCH + b] & m3);
                if (rn == 0u)   // add updated-data contribution
                    corr += pair_term(b, u + b * BITD, u + i * BITD);
            }
            if (corr != 0.0) atomicAdd(&g_corr, corr);

            float dsq = 0.f;
            if (t < BITD) {
                float a = u[i * BITD + t];
                float c = U[(size_t)n * BITD + t];
                atomicAdd(&g_SUpad[t * 16], (double)(a - c));
                dsq = a * a - c * c;
                dsq = wred(dsq);
                if (lane == 0) atomicAdd(&g_SUsq, (double)dsq);
            }
        }
    }

    // ================= finalize tail: last block to finish ===============
    __threadfence();
    __syncthreads();
    if (t == 0)
        s_flag = (atomicAdd(&g_done, 1u) == MEGA_BLOCKS - 1) ? 1 : 0;
    __syncthreads();
    if (!s_flag) return;
    __threadfence();

    __shared__ double sterm[BITD];
    __shared__ double sparts[8];

    if (t < BITD) {
        double s = 0.0;
#pragma unroll 8
        for (int i = 0; i < BATCH_BLOCKS; i++)
            s += (double)g_supart[i * BITD + t];
        sterm[t] = s * g_SUpad[t * 16];
    }
    if (t < BATCH_BLOCKS) {
        double q = wredd((double)g_uqpart[t]);
        double a = wredd((double)g_s2part[t]);
        if (lane == 0) { sparts[warp] = q; sparts[4 + warp] = a; }
    }
    __syncthreads();

    if (t == 0) {
        double dotsum = 0.0;
#pragma unroll
        for (int k = 0; k < BITD; k++) dotsum += sterm[k];
        double sum_usq = sparts[0] + sparts[1] + sparts[2] + sparts[3];
        double s2sum   = sparts[4] + sparts[5] + sparts[6] + sparts[7];
        double sum_dist = (double)NTRAIN * sum_usq
                        + (double)BATCH  * g_SUsq
                        - 2.0 * dotsum;
        double loss1 = (0.5 * sum_dist + g_corr)
                     / ((double)BATCH * (double)NTRAIN);
        double loss2 = 0.1 * s2sum / ((double)BATCH * (double)BITD);
        out[0] = (float)(loss1 + loss2);
    }
}

// ------------------------------------------------------------ launcher
extern "C" void kernel_launch(void* const* d_in, const int* in_sizes, int n_in,
                              void* d_out, int out_size) {
    const float* u   = (const float*)d_in[0];   // [512, 64]
    const float* y   = (const float*)d_in[1];   // [512, 100]
    const int*   ind = (const int*)  d_in[2];   // [512]
    const float* U   = (const float*)d_in[3];   // [100000, 64]
    const float* Y   = (const float*)d_in[4];   // [100000, 100]
    float* out = (float*)d_out;

    k_pb<<<PB_BLOCKS, 256>>>(u, y, Y);
    k_mega<<<MEGA_BLOCKS, 256>>>(u, ind, U, Y, out);
}

// round 16
// speedup vs baseline: 1.9585x; 1.0466x over previous
#include <cuda_runtime.h>
#include <cstdint>

#define BATCH    512
#define BITD     64
#define NCLS     100
#define NTRAIN   100000
#define MARGIN_F 128.0f

#define PACK_BLOCKS  391         // 256 rows per block
#define BATCH_BLOCKS 128         // 4 batch rows per block
#define PB_BLOCKS    (PACK_BLOCKS + BATCH_BLOCKS)

#define SCAN_BLOCKS  1564        // 64 n per block, 4 threads per n
#define UST_BLOCKS   512
#define FIX_BLOCKS   512         // 1 batch row per block
#define MEGA_BLOCKS  (SCAN_BLOCKS + UST_BLOCKS + FIX_BLOCKS)

#define Y_U4_TOTAL   (NTRAIN * 25)   // Y as uint4 count (400B rows)

// -------- device accumulators / scratch (no allocations allowed) --------
__device__ double   g_SUsq;           // sum_n |U'_n|^2 (ust + fix deltas)
__device__ double   g_corr;           // hinge corrections over mismatch pairs
__device__ double   g_SUpad[BITD * 16]; // padded col sums (1 dbl / 128B line)
__device__ float    g_usq[BATCH];     // per-row |u_b|^2
__device__ __align__(16) unsigned g_ypk[4 * BATCH];  // batch packs [word][row]
__device__ uint4    g_ypkN[NTRAIN];   // packed training labels, one uint4/row
__device__ __align__(16) float g_supart[BATCH_BLOCKS * BITD]; // u col partials
__device__ float    g_uqpart[BATCH_BLOCKS];  // per-block sum |u|^2 partials
__device__ float    g_s2part[BATCH_BLOCKS];  // per-block s2 partials
__device__ unsigned g_done;           // k_mega completion counter

__device__ __forceinline__ float wred(float v) {
#pragma unroll
    for (int o = 16; o; o >>= 1) v += __shfl_xor_sync(0xffffffffu, v, o);
    return v;
}
__device__ __forceinline__ double wredd(double v) {
#pragma unroll
    for (int o = 16; o; o >>= 1) v += __shfl_xor_sync(0xffffffffu, v, o);
    return v;
}

// --------- rare path: exact pair term 0.5*(max(m-d,0) - d) --------------
// Serial FMA chain: identical FP-op order wherever compiled -> the
// add-then-subtract cancellation across scan/fix roles is bit-exact.
__device__ __noinline__ double pair_term(int b, const float* __restrict__ ur,
                                         const float* __restrict__ vr) {
    float dot = 0.f, vsq = 0.f;
#pragma unroll 16
    for (int k = 0; k < BITD; k++) {
        float a = ur[k], c = vr[k];
        dot = fmaf(a, c, dot);
        vsq = fmaf(c, c, vsq);
    }
    float d = g_usq[b] - 2.f * dot + vsq;
    d = fmaxf(d, 0.f);
    return 0.5 * ((double)fmaxf(MARGIN_F - d, 0.f) - (double)d);
}

// Permuted pack mapping (identical everywhere): class c -> word (c&3),
// bit (c>>2). Set intersection is permutation-invariant.
template<int Q>
__device__ __forceinline__ void pack25(const unsigned* __restrict__ sw,
                                       unsigned& p0, unsigned& p1,
                                       unsigned& p2, unsigned& p3) {
#pragma unroll
    for (int i = 0; i < 25; i++) {
        const int c = Q * 25 + i;                 // compile-time
        const unsigned m = 1u << (c >> 2);
        if (__uint_as_float(sw[i]) != 0.f) {
            switch (c & 3) {
            case 0: p0 |= m; break;
            case 1: p1 |= m; break;
            case 2: p2 |= m; break;
            case 3: p3 |= m; break;
            }
        }
    }
}

// ballot pack for the batch role (lane l<25 covers classes 4l..4l+3:
// word w bit l <- class 4l+w, same (c&3)/(c>>2) mapping)
__device__ __forceinline__ uint4 pack_ballots(const float* __restrict__ row,
                                              int lane) {
    float4 v = make_float4(0.f, 0.f, 0.f, 0.f);
    if (lane < 25) v = ((const float4*)row)[lane];
    uint4 r;
    r.x = __ballot_sync(0xffffffffu, v.x != 0.f);
    r.y = __ballot_sync(0xffffffffu, v.y != 0.f);
    r.z = __ballot_sync(0xffffffffu, v.z != 0.f);
    r.w = __ballot_sync(0xffffffffu, v.w != 0.f);
    return r;
}

// ---- cp.async helpers ----
template<int N>
__device__ __forceinline__ void cp_wait() {
    asm volatile("cp.async.wait_group %0;" :: "n"(N) : "memory");
}
__device__ __forceinline__ void cp_commit() {
    asm volatile("cp.async.commit_group;" ::: "memory");
}
__device__ __forceinline__ void cp_cg16(unsigned sdst, const void* gsrc) {
    asm volatile("cp.async.cg.shared.global [%0], [%1], 16;"
                 :: "r"(sdst), "l"(gsrc) : "memory");
}

// ------------- pack + batch kernel (R12, validated) ----------------------
__global__ void __launch_bounds__(256)
k_pb(const float* __restrict__ u, const float* __restrict__ y,
     const float* __restrict__ Y) {
    __shared__ __align__(16) unsigned sbuf[3 * 800 * 4];
    __shared__ float scol[BITD];
    __shared__ float sv[8];

    int t    = threadIdx.x;
    int lane = t & 31, warp = t >> 5;

    if (blockIdx.x < PACK_BLOCKS) {
        // ====================== pack role ================================
        const uint4* Y4 = (const uint4*)Y;
        unsigned sb = (unsigned)__cvta_generic_to_shared(sbuf);
        int base4 = blockIdx.x * 6400;            // 256 rows * 25 uint4

        auto issue = [&](int c) {
            unsigned dst = sb + (unsigned)(c % 3) * 12800u;
            int g0 = base4 + c * 800;
#pragma unroll
            for (int j = 0; j < 3; j++) {
                int k = t + j * 256;
                int g = g0 + k;
                if (g >= Y_U4_TOTAL) g = Y_U4_TOTAL - 1;
                cp_cg16(dst + (unsigned)k * 16u, Y4 + g);
            }
            if (t < 32) {
                int k = 768 + t;
                int g = g0 + k;
                if (g >= Y_U4_TOTAL) g = Y_U4_TOTAL - 1;
                cp_cg16(dst + (unsigned)k * 16u, Y4 + g);
            }
            cp_commit();
        };

        issue(0);
        issue(1);

#pragma unroll 1
        for (int c = 0; c < 8; c++) {
            if (c + 2 < 8) issue(c + 2);
            switch (7 - c) {
            case 0:  cp_wait<0>(); break;
            case 1:  cp_wait<1>(); break;
            default: cp_wait<2>(); break;
            }
            __syncthreads();

            if (t < 128) {
                const unsigned* bufw = sbuf + (c % 3) * 3200;
                const unsigned* sw = bufw + t * 25;
                unsigned p0 = 0, p1 = 0, p2 = 0, p3 = 0;
                switch (t & 3) {
                case 0: pack25<0>(sw, p0, p1, p2, p3); break;
                case 1: pack25<1>(sw, p0, p1, p2, p3); break;
                case 2: pack25<2>(sw, p0, p1, p2, p3); break;
                default: pack25<3>(sw, p0, p1, p2, p3); break;
                }
                p0 |= __shfl_xor_sync(0xffffffffu, p0, 1);
                p0 |= __shfl_xor_sync(0xffffffffu, p0, 2);
                p1 |= __shfl_xor_sync(0xffffffffu, p1, 1);
                p1 |= __shfl_xor_sync(0xffffffffu, p1, 2);
                p2 |= __shfl_xor_sync(0xffffffffu, p2, 1);
                p2 |= __shfl_xor_sync(0xffffffffu, p2, 2);
                p3 |= __shfl_xor_sync(0xffffffffu, p3, 1);
                p3 |= __shfl_xor_sync(0xffffffffu, p3, 2);
                if ((t & 3) == 0) {
                    int nr = blockIdx.x * 256 + c * 32 + (t >> 2);
                    if (nr < NTRAIN)
                        g_ypkN[nr] = make_uint4(p0, p1, p2, p3);
                }
            }
            __syncthreads();
        }
    } else {
        // ====================== batch role ===============================
        int bb  = blockIdx.x - PACK_BLOCKS;       // 0..127
        int row = bb * 4 + warp;                  // 0..511

        if (t < BITD) scol[t] = 0.f;
        if (bb == 0) {
            if (t < BITD) g_SUpad[t * 16] = 0.0;
            if (t == 0) { g_SUsq = 0.0; g_corr = 0.0; g_done = 0u; }
        }
        __syncthreads();

        float2 v = ((const float2*)(u + row * BITD))[lane];
        float usq = v.x * v.x + v.y * v.y;
        float s2  = ((v.x > 0.f) ? 0.f : ((v.x < 0.f) ? 2.f : 1.f))
                  + ((v.y > 0.f) ? 0.f : ((v.y < 0.f) ? 2.f : 1.f));
        atomicAdd(&scol[2 * lane],     v.x);
        atomicAdd(&scol[2 * lane + 1], v.y);
        float usqr = wred(usq);
        float s2r  = wred(s2);
        if (lane == 0) { g_usq[row] = usqr; sv[warp] = usqr; sv[4 + warp] = s2r; }

        uint4 b = pack_ballots(y + (size_t)row * NCLS, lane);
        if (lane == 0) {
            g_ypk[row]             = b.x;
            g_ypk[BATCH + row]     = b.y;
            g_ypk[2 * BATCH + row] = b.z;
            g_ypk[3 * BATCH + row] = b.w;
        }
        __syncthreads();

        if (t < BITD) g_supart[bb * BITD + t] = scol[t];
        if (t == 0) {
            g_uqpart[bb] = sv[0] + sv[1] + sv[2] + sv[3];
            g_s2part[bb] = sv[4] + sv[5] + sv[6] + sv[7];
        }
    }
}

// ------------- mega kernel: quad-split scan + U-stats + fix + finalize ---
__global__ void __launch_bounds__(256)
k_mega(const float* __restrict__ u, const int* __restrict__ ind,
       const float* __restrict__ U, const float* __restrict__ Y,
       float* __restrict__ out) {
    __shared__ __align__(16) unsigned sh[4 * BATCH];  // 8KB
    __shared__ int      sind[BATCH];
    __shared__ float    scol[BITD + 8];
    __shared__ unsigned yn4[4];
    __shared__ int      s_last;
    __shared__ int      s_flag;

    int t    = threadIdx.x;
    int lane = t & 31, warp = t >> 5;

    if (blockIdx.x < SCAN_BLOCKS) {
        // ====== scan role: 64 n per block, 4 threads per n ===============
#pragma unroll
        for (int i = 0; i < 2; i++)
            ((uint4*)sh)[t + i * 256] = ((const uint4*)g_ypk)[t + i * 256];

        int n    = blockIdx.x * 64 + (t & 63);    // all quarters same n set
        int quad = t >> 6;                        // 0..3: b-range quarter
        uint4 pk = make_uint4(0u, 0u, 0u, 0u);
        if (n < NTRAIN) pk = g_ypkN[n];           // coalesced (dup in L1)
        unsigned w0 = pk.x, w1 = pk.y, w2 = pk.z, w3 = pk.w;
        __syncthreads();

        if (n < NTRAIN) {
            const uint4* sh4 = (const uint4*)sh;  // word-0 table as uint4
            int bbase = quad * 128;
            double corr = 0.0;
#pragma unroll 4
            for (int bo = 0; bo < 128; bo += 8) {
                int b0i = bbase + bo;
                uint4 pa = sh4[b0i >> 2];
                uint4 pb = sh4[(b0i >> 2) + 1];
                unsigned mna = min(min(pa.x & w0, pa.y & w0),
                                   min(pa.z & w0, pa.w & w0));
                unsigned mnb = min(min(pb.x & w0, pb.y & w0),
                                   min(pb.z & w0, pb.w & w0));
                if (min(mna, mnb) == 0u) {
#pragma unroll 1
                    for (int j = 0; j < 8; j++) {
                        int b = b0i + j;
                        unsigned r = (sh[b] & w0) | (sh[BATCH + b] & w1) |
                                     (sh[2 * BATCH + b] & w2) |
                                     (sh[3 * BATCH + b] & w3);
                        if (r == 0u)
                            corr += pair_term(b, u + b * BITD,
                                              U + (size_t)n * BITD);
                    }
                }
            }
            if (corr != 0.0) atomicAdd(&g_corr, corr);
        }
    } else if (blockIdx.x < SCAN_BLOCKS + UST_BLOCKS) {
        // ================= U stats role ==================================
        const int nth = UST_BLOCKS * 256;                 // 131072
        int gid = (blockIdx.x - SCAN_BLOCKS) * 256 + t;
        const float4* U4 = (const float4*)U;
        const int total4 = NTRAIN * BITD / 4;             // 1.6M

        float c0 = 0.f, c1 = 0.f, c2 = 0.f, c3 = 0.f, sq = 0.f;
#pragma unroll 4
        for (int i = gid; i < total4; i += nth) {
            float4 v = U4[i];
            c0 += v.x; c1 += v.y; c2 += v.z; c3 += v.w;
            sq += v.x * v.x + v.y * v.y + v.z * v.z + v.w * v.w;
        }
        int cbase = (4 * gid) & (BITD - 1);
        c0 += __shfl_xor_sync(0xffffffffu, c0, 16);
        c1 += __shfl_xor_sync(0xffffffffu, c1, 16);
        c2 += __shfl_xor_sync(0xffffffffu, c2, 16);
        c3 += __shfl_xor_sync(0xffffffffu, c3, 16);
        sq = wred(sq);

        if (t < BITD + 8) scol[t] = 0.f;
        __syncthreads();
        if (lane < 16) {
            atomicAdd(&scol[cbase],     c0);
            atomicAdd(&scol[cbase + 1], c1);
            atomicAdd(&scol[cbase + 2], c2);
            atomicAdd(&scol[cbase + 3], c3);
        }
        if (lane == 0) scol[BITD + warp] = sq;
        __syncthreads();
        if (t < BITD) atomicAdd(&g_SUpad[t * 16], (double)scol[t]);
        if (t == 0) {
            float s = 0.f;
#pragma unroll
            for (int w = 0; w < 8; w++) s += scol[BITD + w];
            atomicAdd(&g_SUsq, (double)s);
        }
    } else {
        // ================= fix role: one block per batch row =============
        int i = blockIdx.x - SCAN_BLOCKS - UST_BLOCKS;    // 0..511

        sind[t]       = ind[t];
        sind[t + 256] = ind[t + 256];
#pragma unroll
        for (int j = 0; j < 2; j++)
            ((uint4*)sh)[t + j * 256] = ((const uint4*)g_ypk)[t + j * 256];
        if (t == 0) s_last = 1;
        __syncthreads();

        int n = sind[i];
        for (int j = i + 1 + t; j < BATCH; j += 256)
            if (sind[j] == n) s_last = 0;
        __syncthreads();

        if (s_last) {
            if (t == 0) {
                uint4 b = g_ypkN[n];              // packed original Y row n
                yn4[0] = b.x; yn4[1] = b.y; yn4[2] = b.z; yn4[3] = b.w;
            }
            __syncthreads();

            unsigned yn0 = yn4[0], yn1 = yn4[1], yn2 = yn4[2], yn3 = yn4[3];
            unsigned m0 = sh[i],             m1 = sh[BATCH + i];
            unsigned m2 = sh[2 * BATCH + i], m3 = sh[3 * BATCH + i];
            double corr = 0.0;
#pragma unroll
            for (int bb = 0; bb < 2; bb++) {
                int b = t + bb * 256;
                unsigned ro = (sh[b] & yn0) | (sh[BATCH + b] & yn1) |
                              (sh[2 * BATCH + b] & yn2) |
                              (sh[3 * BATCH + b] & yn3);
                if (ro == 0u)   // remove scan's old-data contribution
                    corr -= pair_term(b, u + b * BITD, U + (size_t)n * BITD);
                unsigned rn = (sh[b] & m0) | (sh[BATCH + b] & m1) |
                              (sh[2 * BATCH + b] & m2) |
                              (sh[3 * BATCH + b] & m3);
                if (rn == 0u)   // add updated-data contribution
                    corr += pair_term(b, u + b * BITD, u + i * BITD);
            }
            if (corr != 0.0) atomicAdd(&g_corr, corr);

            float dsq = 0.f;
            if (t < BITD) {
                float a = u[i * BITD + t];
                float c = U[(size_t)n * BITD + t];
                atomicAdd(&g_SUpad[t * 16], (double)(a - c));
                dsq = a * a - c * c;
                dsq = wred(dsq);
                if (lane == 0) atomicAdd(&g_SUsq, (double)dsq);
            }
        }
    }

    // ================= finalize tail: last block to finish ===============
    __threadfence();
    __syncthreads();
    if (t == 0)
        s_flag = (atomicAdd(&g_done, 1u) == MEGA_BLOCKS - 1) ? 1 : 0;
    __syncthreads();
    if (!s_flag) return;
    __threadfence();

    __shared__ double sterm[BITD];
    __shared__ double sparts[8];

    if (t < BITD) {
        double s = 0.0;
#pragma unroll 8
        for (int i = 0; i < BATCH_BLOCKS; i++)
            s += (double)g_supart[i * BITD + t];
        sterm[t] = s * g_SUpad[t * 16];
    }
    if (t < BATCH_BLOCKS) {
        double q = wredd((double)g_uqpart[t]);
        double a = wredd((double)g_s2part[t]);
        if (lane == 0) { sparts[warp] = q; sparts[4 + warp] = a; }
    }
    __syncthreads();

    if (t == 0) {
        double dotsum = 0.0;
#pragma unroll
        for (int k = 0; k < BITD; k++) dotsum += sterm[k];
        double sum_usq = sparts[0] + sparts[1] + sparts[2] + sparts[3];
        double s2sum   = sparts[4] + sparts[5] + sparts[6] + sparts[7];
        double sum_dist = (double)NTRAIN * sum_usq
                        + (double)BATCH  * g_SUsq
                        - 2.0 * dotsum;
        double loss1 = (0.5 * sum_dist + g_corr)
                     / ((double)BATCH * (double)NTRAIN);
        double loss2 = 0.1 * s2sum / ((double)BATCH * (double)BITD);
        out[0] = (float)(loss1 + loss2);
    }
}

// ------------------------------------------------------------ launcher
extern "C" void kernel_launch(void* const* d_in, const int* in_sizes, int n_in,
                              void* d_out, int out_size) {
    const float* u   = (const float*)d_in[0];   // [512, 64]
    const float* y   = (const float*)d_in[1];   // [512, 100]
    const int*   ind = (const int*)  d_in[2];   // [512]
    const float* U   = (const float*)d_in[3];   // [100000, 64]
    const float* Y   = (const float*)d_in[4];   // [100000, 100]
    float* out = (float*)d_out;

    k_pb<<<PB_BLOCKS, 256>>>(u, y, Y);
    k_mega<<<MEGA_BLOCKS, 256>>>(u, ind, U, Y, out);
}